// round 10
// baseline (speedup 1.0000x reference)
#include <cuda_runtime.h>
#include <math.h>
#include <stdint.h>

#define NB 16
#define CTOT 320
#define DH 160
#define HW 3136

// ---------------- scratch (device globals; no allocation) ----------------
__device__ float g_xp  [NB*CTOT*HW];
__device__ float g_phin[NB*DH*HW];   // x1 + pos_h (precomputed in step-1 epilogue)
__device__ float g_ph  [NB*DH*HW];
__device__ float g_ahT [NB*DH*HW];
__device__ float g_pw  [NB*DH*HW];
__device__ float g_x1o [NB*DH*HW];
__device__ float g_xw  [NB*DH*HW];
__device__ float g_xh  [NB*DH*HW];
__device__ float g_x2o [NB*DH*HW];
__device__ float g_pool[NB*DH];
__device__ float g_att [NB*DH*3];

__device__ __forceinline__ float gelu_f(float v){
    return 0.5f*v*(1.0f+erff(v*0.70710678118654752440f));
}
__device__ __forceinline__ uint32_t tf32_rna(float v){
    uint32_t o;
    asm("cvt.rna.tf32.f32 %0, %1;" : "=r"(o) : "f"(v));
    return o;
}
__device__ __forceinline__ void mma_tf32(float* c, const uint32_t* a, const uint32_t* b){
    asm volatile(
        "mma.sync.aligned.m16n8k8.row.col.f32.tf32.tf32.f32 "
        "{%0,%1,%2,%3}, {%4,%5,%6,%7}, {%8,%9}, {%0,%1,%2,%3};"
        : "+f"(c[0]), "+f"(c[1]), "+f"(c[2]), "+f"(c[3])
        : "r"(a[0]), "r"(a[1]), "r"(a[2]), "r"(a[3]), "r"(b[0]), "r"(b[1]));
}
#define CP16(dst, src) \
    asm volatile("cp.async.ca.shared.global [%0], [%1], 16;" :: "r"(dst), "l"(src))
#define CP_COMMIT() asm volatile("cp.async.commit_group;" ::: "memory")
#define CP_WAIT2()  asm volatile("cp.async.wait_group 2;" ::: "memory")

// SMEM: A stages 4 x [64][20]  (stride 20 -> 32 distinct banks for 8rx4c frag)
//       B stages 4 x [16][264] (stride 264 = 8 mod 32 -> conflict-free 4rx8c frag)
#define A_STRIDE 20
#define B2_STRIDE 264
#define A_STAGE  (64*A_STRIDE)           // 1280 floats
#define B_STAGE  (16*B2_STRIDE)          // 4224 floats
#define B_BASE   (4*A_STAGE)             // 5120 floats
#define SMEM_GEMM ((4*A_STAGE + 4*B_STAGE)*4)   // 88064 bytes

// =================================================================================
// HMMA tf32 GEMM, 4-stage cp.async pipeline, block 64ch x 256cols, 8 warps (2Mx4N),
// warp tile 32x64 (2 x m16 by 8 x n8). K=320 in 20 chunks of 16.
// Optional dual output for step 1: out2 = v + emb2 (pos_h fold, ch<160).
// =================================================================================
__global__ __launch_bounds__(256, 2) void gemm_mma(
    const float* __restrict__ Wm, int M,
    const float* __restrict__ bias,
    const float* __restrict__ in0, long bs0,
    const float* __restrict__ in1, long bs1, int split,
    const float* __restrict__ bn_s, const float* __restrict__ bn_b,
    const float* __restrict__ bn_m, const float* __restrict__ bn_v,
    const float* __restrict__ emb,
    float* __restrict__ out, long obs, int transOut, int doGelu,
    const float* __restrict__ emb2, float* __restrict__ out2)
{
    extern __shared__ float smf[];
    uint32_t sbase = (uint32_t)__cvta_generic_to_shared(smf);

    const int tid  = threadIdx.x;
    const int wid  = tid >> 5;
    const int lane = tid & 31;
    const int gidq = lane >> 2;
    const int tig  = lane & 3;
    const int wm   = wid >> 2;    // 0..1 : 32-row half
    const int wn   = wid & 3;     // 0..3 : 64-col quarter

    const long gp0 = (long)blockIdx.x * 256;
    const int  m0  = blockIdx.y * 64;

    float acc[2][8][4];
    #pragma unroll
    for (int mi=0;mi<2;mi++)
        #pragma unroll
        for (int ni=0;ni<8;ni++)
            #pragma unroll
            for (int r=0;r<4;r++) acc[mi][ni][r]=0.f;

    // ---- A-load coords: 64x16 tile, 1 CP16/thread ----
    const int arow = tid >> 2;
    const int akq  = (tid & 3) * 4;
    int ach = m0 + arow; if (ach > M-1) ach = M-1;
    const float* asrc_base = Wm + (long)ach*320 + akq;

    // ---- B-load coords: 16x256 tile, 4 CP16/thread ----
    const long gpb = gp0 + (tid & 63) * 4;
    const int  bn_ = (int)(gpb / HW);
    const int  bp_ = (int)(gpb - (long)bn_ * HW);
    const float* bptr0 = in0 + (long)bn_*bs0 + bp_;
    const float* bptr1 = in1 + (long)bn_*bs1 + bp_;
    const int bkr0 = tid >> 6;             // 0..3 ; rows bkr0 + 4r

    auto load_chunk = [&](int kc, int s){
        CP16(sbase + (uint32_t)((s*A_STAGE + arow*A_STRIDE + akq)*4),
             asrc_base + kc*16);
        #pragma unroll
        for (int r = 0; r < 4; r++) {
            int kr = bkr0 + r*4;
            int c  = kc*16 + kr;
            const float* src = (c < split) ? (bptr0 + (long)c*HW)
                                           : (bptr1 + (long)(c-split)*HW);
            CP16(sbase + (uint32_t)((B_BASE + s*B_STAGE + kr*B2_STRIDE + (tid&63)*4)*4),
                 src);
        }
    };

    #pragma unroll
    for (int i = 0; i < 3; i++) { load_chunk(i, i); CP_COMMIT(); }

    for (int i = 0; i < 20; i++) {
        CP_WAIT2();
        __syncthreads();
        if (i + 3 < 20) load_chunk(i+3, (i+3) & 3);
        CP_COMMIT();

        const int s = i & 3;
        const float* Af = smf + s*A_STAGE;
        const float* Bf = smf + B_BASE + s*B_STAGE;
        #pragma unroll
        for (int ks = 0; ks < 2; ks++) {
            int kb = ks * 8;
            uint32_t a[2][4];
            #pragma unroll
            for (int mi=0;mi<2;mi++) {
                int mr = wm*32 + mi*16;
                a[mi][0] = tf32_rna(Af[(mr+gidq  )*A_STRIDE + kb+tig  ]);
                a[mi][1] = tf32_rna(Af[(mr+gidq+8)*A_STRIDE + kb+tig  ]);
                a[mi][2] = tf32_rna(Af[(mr+gidq  )*A_STRIDE + kb+tig+4]);
                a[mi][3] = tf32_rna(Af[(mr+gidq+8)*A_STRIDE + kb+tig+4]);
            }
            uint32_t b[8][2];
            #pragma unroll
            for (int ni=0;ni<8;ni++) {
                int nc = wn*64 + ni*8 + gidq;
                b[ni][0] = tf32_rna(Bf[(kb+tig  )*B2_STRIDE + nc]);
                b[ni][1] = tf32_rna(Bf[(kb+tig+4)*B2_STRIDE + nc]);
            }
            #pragma unroll
            for (int mi=0;mi<2;mi++)
                #pragma unroll
                for (int ni=0;ni<8;ni++)
                    mma_tf32(acc[mi][ni], a[mi], b[ni]);
        }
    }

    // ---- epilogue (coords recomputed inline to limit register pressure) ----
    #pragma unroll
    for (int mi=0;mi<2;mi++) {
        #pragma unroll
        for (int half=0;half<2;half++) {
            int ch = m0 + wm*32 + mi*16 + gidq + half*8;
            if (ch >= M) continue;
            float bi = bias ? bias[ch] : 0.f;
            float sc = 1.f, be = 0.f;
            if (bn_s) { sc = bn_s[ch]*rsqrtf(bn_v[ch]+1e-5f); be = bn_b[ch]-bn_m[ch]*sc; }
            long chbase = (long)ch * HW;
            #pragma unroll
            for (int ni=0;ni<8;ni++) {
                #pragma unroll
                for (int c2=0;c2<2;c2++) {
                    int j = wn*64 + ni*8 + 2*tig + c2;
                    long gp = gp0 + j;
                    int n = (int)(gp / HW);
                    int p = (int)(gp - (long)n * HW);
                    int h = p / 56, w = p % 56;
                    int d = w - h; d = min(max(d,-56),56); d += 56;
                    float v = acc[mi][ni][half*2+c2] + bi;
                    if (bn_s) v = v*sc + be;
                    if (doGelu) v = gelu_f(v);
                    if (emb) v += emb[d*DH + ch];
                    out[(long)n*obs + chbase + (transOut ? (w*56+h) : p)] = v;
                    if (out2 && ch < DH)
                        out2[(long)n*((long)DH*HW) + chbase + p] = v + emb2[d*DH + ch];
                }
            }
        }
    }
}

// =================================================================================
// Strip grouped conv as HMMA tf32 GEMM — double-buffered, register-staged gather.
// (unchanged from R8 — passing, 64us/call)
// =================================================================================
__global__ __launch_bounds__(256, 3) void strip_mma(
    const float* __restrict__ xin, long in_bs,
    const float* __restrict__ Wt, const float* __restrict__ Bias,
    float* __restrict__ out, long out_bs, int transOut)
{
    __shared__ uint32_t As[2][64][17];
    __shared__ uint32_t Bs[2][16][132];

    const int tid  = threadIdx.x;
    const int wid  = tid >> 5;
    const int lane = tid & 31;
    const int gidq = lane >> 2;
    const int tig  = lane & 3;
    const int wm   = wid >> 2;
    const int wn   = wid & 3;

    const int jb   = blockIdx.x * 128;
    const int ci2  = blockIdx.y;

    float acc[2][4][4];
    #pragma unroll
    for (int mi=0;mi<2;mi++)
        #pragma unroll
        for (int ni=0;ni<4;ni++)
            #pragma unroll
            for (int r=0;r<4;r++) acc[mi][ni][r]=0.f;

    const int arow = tid >> 2;
    const int akq  = (tid & 3) * 4;
    const float* wbase = Wt + (long)ci2 * 9408 + (long)arow * 168;

    int bn_[2], bc1_[2], bx0_[2], bkr_[2];
    #pragma unroll
    for (int r = 0; r < 2; r++) {
        bkr_[r] = (tid >> 5) + r*8;
        int j   = jb + (tid & 31) * 4;
        int n   = j / 112;
        int rem = j - n*112;
        bn_[r]  = n;
        bc1_[r] = rem / 56;
        bx0_[r] = rem % 56;
    }
    const long nbase0 = (long)bn_[0]*in_bs;

    float areg[4];
    float breg[2][4];

    auto gather = [&](int kc){
        int k0 = kc*16;
        #pragma unroll
        for (int e = 0; e < 4; e++) {
            int k = k0 + akq + e;
            areg[e] = (arow < 56 && k < 168) ? wbase[k] : 0.f;
        }
        #pragma unroll
        for (int r = 0; r < 2; r++) {
            int k = k0 + bkr_[r];
            #pragma unroll
            for (int e = 0; e < 4; e++) breg[r][e] = 0.f;
            if (k < 168) {
                int i  = k / 3;
                int kk = k - 3*i;
                int f  = ci2*56 + i;
                int pos2 = f / 80;
                int ch   = bc1_[r]*80 + (f - pos2*80);
                const float* src = xin + nbase0 + (long)ch*HW + pos2*56;
                int xs0 = bx0_[r] + kk - 1;
                #pragma unroll
                for (int e = 0; e < 4; e++) {
                    int xs = xs0 + e;
                    if (xs >= 0 && xs < 56) breg[r][e] = src[xs];
                }
            }
        }
    };
    auto stage = [&](int s){
        #pragma unroll
        for (int e = 0; e < 4; e++) As[s][arow][akq+e] = tf32_rna(areg[e]);
        #pragma unroll
        for (int r = 0; r < 2; r++) {
            uint4 tv;
            tv.x = tf32_rna(breg[r][0]); tv.y = tf32_rna(breg[r][1]);
            tv.z = tf32_rna(breg[r][2]); tv.w = tf32_rna(breg[r][3]);
            *(uint4*)&Bs[s][bkr_[r]][(tid & 31)*4] = tv;
        }
    };

    gather(0);
    for (int c = 0; c < 11; c++) {
        const int s = c & 1;
        stage(s);
        if (c < 10) gather(c+1);
        __syncthreads();
        #pragma unroll
        for (int ks = 0; ks < 2; ks++) {
            int kb = ks * 8;
            uint32_t a[2][4];
            #pragma unroll
            for (int mi=0;mi<2;mi++) {
                int mr = wm*32 + mi*16;
                a[mi][0] = As[s][mr+gidq  ][kb+tig  ];
                a[mi][1] = As[s][mr+gidq+8][kb+tig  ];
                a[mi][2] = As[s][mr+gidq  ][kb+tig+4];
                a[mi][3] = As[s][mr+gidq+8][kb+tig+4];
            }
            uint32_t b[4][2];
            #pragma unroll
            for (int ni=0;ni<4;ni++) {
                int nc = wn*32 + ni*8 + gidq;
                b[ni][0] = Bs[s][kb+tig  ][nc];
                b[ni][1] = Bs[s][kb+tig+4][nc];
            }
            #pragma unroll
            for (int mi=0;mi<2;mi++)
                #pragma unroll
                for (int ni=0;ni<4;ni++)
                    mma_tf32(acc[mi][ni], a[mi], b[ni]);
        }
    }

    long co_base[8]; int co_x[8];
    #pragma unroll
    for (int ni=0;ni<4;ni++) {
        #pragma unroll
        for (int c2=0;c2<2;c2++) {
            int j = jb + wn*32 + ni*8 + 2*tig + c2;
            int n   = j / 112;
            int rem = j - n*112;
            int c1  = rem / 56;
            co_x[ni*2+c2]    = rem % 56;
            co_base[ni*2+c2] = (long)n*out_bs + (long)(c1*80 + ci2)*HW;
        }
    }
    #pragma unroll
    for (int mi=0;mi<2;mi++) {
        #pragma unroll
        for (int half=0;half<2;half++) {
            int o2 = wm*32 + mi*16 + gidq + half*8;
            if (o2 >= 56) continue;
            float bv = Bias[ci2*56 + o2];
            #pragma unroll
            for (int ni=0;ni<4;ni++) {
                #pragma unroll
                for (int c2=0;c2<2;c2++) {
                    int q = ni*2+c2;
                    int x = co_x[q];
                    float v = acc[mi][ni][half*2+c2] + bv;
                    out[co_base[q] + (transOut ? (x*56+o2) : (o2*56+x))] = v;
                }
            }
        }
    }
}

// ---------------- depthwise 3x7 + 7x3 + pooled sum (unchanged) ----------------
__global__ void dw_kernel(
    const float* __restrict__ xp,
    const float* __restrict__ w37, const float* __restrict__ w73,
    float* __restrict__ xw_o, float* __restrict__ xh_o,
    float* __restrict__ pool)
{
    __shared__ float sp[62*62];
    __shared__ float s37[21], s73[21];
    __shared__ float red[256];
    int b = blockIdx.x;
    int n = b / 160, c = b % 160;
    int tid = threadIdx.x;
    const float* src = xp + (long)n*CTOT*HW + (long)(DH+c)*HW;
    for (int idx = tid; idx < 62*62; idx += 256) {
        int hp = idx/62, wp = idx%62;
        int h = hp-3, w = wp-3;
        sp[idx] = (h>=0 && h<56 && w>=0 && w<56) ? src[h*56+w] : 0.f;
    }
    if (tid < 21) s37[tid] = w37[c*21+tid];
    else if (tid < 42) s73[tid-21] = w73[c*21+tid-21];
    __syncthreads();

    float local = 0.f;
    long obase = (long)n*DH*HW + (long)c*HW;
    for (int g = tid; g < 784; g += 256) {
        int h  = g / 14;
        int w0 = (g % 14)*4;
        float a1[4] = {0,0,0,0};
        float a2[4] = {0,0,0,0};
        #pragma unroll
        for (int kh=0;kh<3;kh++) {
            float xv[10];
            #pragma unroll
            for (int t=0;t<10;t++) xv[t] = sp[(h+kh+2)*62 + w0 + t];
            #pragma unroll
            for (int kw=0;kw<7;kw++) {
                float wv = s37[kh*7+kw];
                #pragma unroll
                for (int l=0;l<4;l++) a1[l] += xv[kw+l]*wv;
            }
        }
        #pragma unroll
        for (int kh=0;kh<7;kh++) {
            float xv[6];
            #pragma unroll
            for (int t=0;t<6;t++) xv[t] = sp[(h+kh)*62 + w0 + 2 + t];
            #pragma unroll
            for (int kw=0;kw<3;kw++) {
                float wv = s73[kh*3+kw];
                #pragma unroll
                for (int l=0;l<4;l++) a2[l] += xv[kw+l]*wv;
            }
        }
        #pragma unroll
        for (int l=0;l<4;l++) {
            int p = h*56 + w0 + l;
            float cv = sp[(h+3)*62 + (w0+3+l)];
            xw_o[obase + p] = a1[l];
            xh_o[obase + p] = a2[l];
            local += a1[l] + a2[l] + cv;
        }
    }
    red[tid] = local;
    __syncthreads();
    for (int s=128; s>0; s>>=1) { if (tid < s) red[tid] += red[tid+s]; __syncthreads(); }
    if (tid==0) pool[n*DH+c] = red[0];
}

// ---------------- attention MLP + softmax (unchanged) ----------------
__global__ void att_kernel(
    const float* __restrict__ pool,
    const float* __restrict__ fc1w, const float* __restrict__ fc1b,
    const float* __restrict__ fc2w, const float* __restrict__ fc2b,
    float* __restrict__ att)
{
    __shared__ float mean_s[160];
    __shared__ float t1[40];
    int n = blockIdx.x;
    int tid = threadIdx.x;
    if (tid < 160) mean_s[tid] = pool[n*160+tid] * (1.0f/3136.0f);
    __syncthreads();
    if (tid < 40) {
        float s = fc1b[tid];
        for (int c=0;c<160;c++) s += fc1w[tid*160+c]*mean_s[c];
        t1[tid] = gelu_f(s);
    }
    __syncthreads();
    if (tid < 160) {
        float a[3];
        #pragma unroll
        for (int s3=0;s3<3;s3++) {
            int k = tid*3+s3;
            float v = fc2b[k];
            for (int j=0;j<40;j++) v += fc2w[k*40+j]*t1[j];
            a[s3]=v;
        }
        float mx = fmaxf(a[0],fmaxf(a[1],a[2]));
        float e0=expf(a[0]-mx), e1=expf(a[1]-mx), e2=expf(a[2]-mx);
        float inv = 1.f/(e0+e1+e2);
        att[(n*160+tid)*3+0]=e0*inv;
        att[(n*160+tid)*3+1]=e1*inv;
        att[(n*160+tid)*3+2]=e2*inv;
    }
}

// ---------------- x2_out combine (float4 vectorized) ----------------
__global__ void x2out_kernel(
    const float* __restrict__ xp, const float* __restrict__ xw,
    const float* __restrict__ xh, const float* __restrict__ att,
    float* __restrict__ x2o)
{
    long idx4 = (long)blockIdx.x*blockDim.x + threadIdx.x;
    const long total4 = (long)NB*DH*HW/4;
    if (idx4 >= total4) return;
    long idx = idx4 * 4;
    long t = idx / HW;           // HW % 4 == 0, so 4-vector stays in one plane
    int p = (int)(idx - t*HW);
    int c = (int)(t % DH);
    int n = (int)(t / DH);
    const float* a = att + ((long)n*DH + c)*3;
    float a0 = a[0], a1 = a[1], a2 = a[2];
    float4 xh4 = *(const float4*)(xh + idx);
    float4 xw4 = *(const float4*)(xw + idx);
    float4 x24 = *(const float4*)(xp + (long)n*CTOT*HW + (long)(DH+c)*HW + p);
    float4 o;
    o.x = xh4.x*a0 + xw4.x*a1 + x24.x*a2;
    o.y = xh4.y*a0 + xw4.y*a1 + x24.y*a2;
    o.z = xh4.z*a0 + xw4.z*a1 + x24.z*a2;
    o.w = xh4.w*a0 + xw4.w*a1 + x24.w*a2;
    *(float4*)(x2o + idx) = o;
}

// ---------------- launch ----------------
extern "C" void kernel_launch(void* const* d_in, const int* in_sizes, int n_in,
                              void* d_out, int out_size)
{
    const float* x           = (const float*)d_in[0];
    const float* mlp_pre_w   = (const float*)d_in[1];
    const float* mlp_pre_b   = (const float*)d_in[2];
    const float* bn0_s = (const float*)d_in[3];
    const float* bn0_b = (const float*)d_in[4];
    const float* bn0_m = (const float*)d_in[5];
    const float* bn0_v = (const float*)d_in[6];
    const float* proj_h_w = (const float*)d_in[7];
    const float* proj_h_b = (const float*)d_in[8];
    const float* proj_w_w = (const float*)d_in[9];
    const float* proj_w_b = (const float*)d_in[10];
    const float* fuse_h_w = (const float*)d_in[11];
    const float* fuse_w_w = (const float*)d_in[12];
    const float* bnh_s = (const float*)d_in[13];
    const float* bnh_b = (const float*)d_in[14];
    const float* bnh_m = (const float*)d_in[15];
    const float* bnh_v = (const float*)d_in[16];
    const float* fc_h_w = (const float*)d_in[17];
    const float* fc_w_w = (const float*)d_in[18];
    const float* rw1w = (const float*)d_in[19];
    const float* rw1b = (const float*)d_in[20];
    const float* rw2w = (const float*)d_in[21];
    const float* rw2b = (const float*)d_in[22];
    const float* fuse_post_w = (const float*)d_in[23];
    const float* emb_h = (const float*)d_in[24];
    const float* emb_w = (const float*)d_in[25];

    float *xp,*phin,*ph,*ahT,*pw,*x1o,*xw,*xh,*x2o,*pool,*att;
    cudaGetSymbolAddress((void**)&xp,  g_xp);
    cudaGetSymbolAddress((void**)&phin,g_phin);
    cudaGetSymbolAddress((void**)&ph,  g_ph);
    cudaGetSymbolAddress((void**)&ahT, g_ahT);
    cudaGetSymbolAddress((void**)&pw,  g_pw);
    cudaGetSymbolAddress((void**)&x1o, g_x1o);
    cudaGetSymbolAddress((void**)&xw,  g_xw);
    cudaGetSymbolAddress((void**)&xh,  g_xh);
    cudaGetSymbolAddress((void**)&x2o, g_x2o);
    cudaGetSymbolAddress((void**)&pool,g_pool);
    cudaGetSymbolAddress((void**)&att, g_att);

    cudaFuncSetAttribute(gemm_mma, cudaFuncAttributeMaxDynamicSharedMemorySize, SMEM_GEMM);

    const long bsX = (long)CTOT*HW;
    const long bsH = (long)DH*HW;

    // 1) xp = gelu(bn(mlp_pre)) ; phin = x1 + pos_h  (dual output)
    gemm_mma<<<dim3(196,5),256,SMEM_GEMM>>>(mlp_pre_w, 320, mlp_pre_b, x, bsX, x, bsX, 320,
                                  bn0_s,bn0_b,bn0_m,bn0_v, nullptr, xp, bsX, 0, 1,
                                  emb_h, phin);
    // 2) strip-H on phin -> ph
    strip_mma<<<dim3(14,80),256>>>(phin, bsH, proj_h_w, proj_h_b, ph, bsH, 0);
    // 3) ahT = T( gelu(bn_h(fuse_h_w @ [ph;x1])) + pos_w )
    gemm_mma<<<dim3(196,3),256,SMEM_GEMM>>>(fuse_h_w, 160, nullptr, ph, bsH, xp, bsX, 160,
                                  bnh_s,bnh_b,bnh_m,bnh_v, emb_w, ahT, bsH, 1, 1,
                                  nullptr, nullptr);
    // 4) strip-W on ahT -> pw
    strip_mma<<<dim3(14,80),256>>>(ahT, bsH, proj_w_w, proj_w_b, pw, bsH, 1);
    // 5) x1_out = fuse_w_w @ [x1;pw]
    gemm_mma<<<dim3(196,3),256,SMEM_GEMM>>>(fuse_w_w, 160, nullptr, xp, bsX, pw, bsH, 160,
                                  nullptr,nullptr,nullptr,nullptr, nullptr, x1o, bsH, 0, 0,
                                  nullptr, nullptr);
    // 6) depthwise paths + pooled sums
    dw_kernel<<<2560,256>>>(xp, fc_h_w, fc_w_w, xw, xh, pool);
    // 7) attention weights
    att_kernel<<<16,160>>>(pool, rw1w, rw1b, rw2w, rw2b, att);
    // 8) x2_out (float4)
    x2out_kernel<<<(int)(((long)NB*DH*HW/4 + 255)/256),256>>>(xp, xw, xh, att, x2o);
    // 9) out = fuse_post_w @ [x1_out;x2_out]
    gemm_mma<<<dim3(196,5),256,SMEM_GEMM>>>(fuse_post_w, 320, nullptr, x1o, bsH, x2o, bsH, 160,
                                  nullptr,nullptr,nullptr,nullptr, nullptr, (float*)d_out, bsX, 0, 0,
                                  nullptr, nullptr);
}

// round 11
// speedup vs baseline: 1.0520x; 1.0520x over previous
#include <cuda_runtime.h>
#include <math.h>
#include <stdint.h>

#define NB 16
#define CTOT 320
#define DH 160
#define HW 3136

// ---------------- scratch (device globals; no allocation) ----------------
__device__ float g_xp  [NB*CTOT*HW];
__device__ float g_phin[NB*DH*HW];   // x1 + pos_h (precomputed in step-1 epilogue)
__device__ float g_ph  [NB*DH*HW];
__device__ float g_ahT [NB*DH*HW];
__device__ float g_pw  [NB*DH*HW];
__device__ float g_x1o [NB*DH*HW];
__device__ float g_xw  [NB*DH*HW];
__device__ float g_xh  [NB*DH*HW];
__device__ float g_x2o [NB*DH*HW];
__device__ float g_pool[NB*DH];
__device__ float g_att [NB*DH*3];

__device__ __forceinline__ float gelu_f(float v){
    return 0.5f*v*(1.0f+erff(v*0.70710678118654752440f));
}
__device__ __forceinline__ uint32_t tf32_rna(float v){
    uint32_t o;
    asm("cvt.rna.tf32.f32 %0, %1;" : "=r"(o) : "f"(v));
    return o;
}
__device__ __forceinline__ void mma_tf32(float* c, const uint32_t* a, const uint32_t* b){
    asm volatile(
        "mma.sync.aligned.m16n8k8.row.col.f32.tf32.tf32.f32 "
        "{%0,%1,%2,%3}, {%4,%5,%6,%7}, {%8,%9}, {%0,%1,%2,%3};"
        : "+f"(c[0]), "+f"(c[1]), "+f"(c[2]), "+f"(c[3])
        : "r"(a[0]), "r"(a[1]), "r"(a[2]), "r"(a[3]), "r"(b[0]), "r"(b[1]));
}
#define CP16(dst, src) \
    asm volatile("cp.async.ca.shared.global [%0], [%1], 16;" :: "r"(dst), "l"(src))
#define CP_COMMIT() asm volatile("cp.async.commit_group;" ::: "memory")
#define CP_WAIT2()  asm volatile("cp.async.wait_group 2;" ::: "memory")

// R8 (682us) gemm geometry: A stages 4 x [64][20], B stages 4 x [16][136]
#define A_STRIDE 20
#define B_STRIDE 136
#define A_STAGE  (64*A_STRIDE)
#define B_STAGE  (16*B_STRIDE)
#define B_BASE   (4*A_STAGE)
#define SMEM_GEMM ((4*A_STAGE + 4*B_STAGE)*4)

// =================================================================================
// HMMA tf32 GEMM, 4-stage cp.async pipeline, block 64ch x 128cols (R8 config).
// Optional dual output for step 1: out2 = v + emb2 (pos_h fold, ch<160).
// =================================================================================
__global__ __launch_bounds__(256, 2) void gemm_mma(
    const float* __restrict__ Wm, int M,
    const float* __restrict__ bias,
    const float* __restrict__ in0, long bs0,
    const float* __restrict__ in1, long bs1, int split,
    const float* __restrict__ bn_s, const float* __restrict__ bn_b,
    const float* __restrict__ bn_m, const float* __restrict__ bn_v,
    const float* __restrict__ emb,
    float* __restrict__ out, long obs, int transOut, int doGelu,
    const float* __restrict__ emb2, float* __restrict__ out2)
{
    extern __shared__ float smf[];
    uint32_t sbase = (uint32_t)__cvta_generic_to_shared(smf);

    const int tid  = threadIdx.x;
    const int wid  = tid >> 5;
    const int lane = tid & 31;
    const int gidq = lane >> 2;
    const int tig  = lane & 3;
    const int wm   = wid >> 2;
    const int wn   = wid & 3;

    const long gp0 = (long)blockIdx.x * 128;
    const int  m0  = blockIdx.y * 64;

    float acc[2][4][4];
    #pragma unroll
    for (int mi=0;mi<2;mi++)
        #pragma unroll
        for (int ni=0;ni<4;ni++)
            #pragma unroll
            for (int r=0;r<4;r++) acc[mi][ni][r]=0.f;

    const int arow = tid >> 2;
    const int akq  = (tid & 3) * 4;
    int ach = m0 + arow; if (ach > M-1) ach = M-1;
    const float* asrc_base = Wm + (long)ach*320 + akq;

    const long gpb = gp0 + (tid & 31) * 4;
    const int  bn_ = (int)(gpb / HW);
    const int  bp_ = (int)(gpb - (long)bn_ * HW);
    const float* bptr0 = in0 + (long)bn_*bs0 + bp_;
    const float* bptr1 = in1 + (long)bn_*bs1 + bp_;
    const int bkr0 = tid >> 5;

    auto load_chunk = [&](int kc, int s){
        CP16(sbase + (uint32_t)((s*A_STAGE + arow*A_STRIDE + akq)*4),
             asrc_base + kc*16);
        #pragma unroll
        for (int r = 0; r < 2; r++) {
            int kr = bkr0 + r*8;
            int c  = kc*16 + kr;
            const float* src = (c < split) ? (bptr0 + (long)c*HW)
                                           : (bptr1 + (long)(c-split)*HW);
            CP16(sbase + (uint32_t)((B_BASE + s*B_STAGE + kr*B_STRIDE + (tid&31)*4)*4),
                 src);
        }
    };

    #pragma unroll
    for (int i = 0; i < 3; i++) { load_chunk(i, i); CP_COMMIT(); }

    for (int i = 0; i < 20; i++) {
        CP_WAIT2();
        __syncthreads();
        if (i + 3 < 20) load_chunk(i+3, (i+3) & 3);
        CP_COMMIT();

        const int s = i & 3;
        const float* Af = smf + s*A_STAGE;
        const float* Bf = smf + B_BASE + s*B_STAGE;
        #pragma unroll
        for (int ks = 0; ks < 2; ks++) {
            int kb = ks * 8;
            uint32_t a[2][4];
            #pragma unroll
            for (int mi=0;mi<2;mi++) {
                int mr = wm*32 + mi*16;
                a[mi][0] = tf32_rna(Af[(mr+gidq  )*A_STRIDE + kb+tig  ]);
                a[mi][1] = tf32_rna(Af[(mr+gidq+8)*A_STRIDE + kb+tig  ]);
                a[mi][2] = tf32_rna(Af[(mr+gidq  )*A_STRIDE + kb+tig+4]);
                a[mi][3] = tf32_rna(Af[(mr+gidq+8)*A_STRIDE + kb+tig+4]);
            }
            uint32_t b[4][2];
            #pragma unroll
            for (int ni=0;ni<4;ni++) {
                int nc = wn*32 + ni*8 + gidq;
                b[ni][0] = tf32_rna(Bf[(kb+tig  )*B_STRIDE + nc]);
                b[ni][1] = tf32_rna(Bf[(kb+tig+4)*B_STRIDE + nc]);
            }
            #pragma unroll
            for (int mi=0;mi<2;mi++)
                #pragma unroll
                for (int ni=0;ni<4;ni++)
                    mma_tf32(acc[mi][ni], a[mi], b[ni]);
        }
    }

    int co_n[8], co_oidx[8], co_d[8], co_p[8];
    #pragma unroll
    for (int ni=0;ni<4;ni++) {
        #pragma unroll
        for (int c2=0;c2<2;c2++) {
            int j = wn*32 + ni*8 + 2*tig + c2;
            long gp = gp0 + j;
            int n = (int)(gp / HW);
            int p = (int)(gp - (long)n * HW);
            int h = p / 56, w = p % 56;
            int d = w - h; d = min(max(d,-56),56);
            co_n[ni*2+c2]   = n;
            co_d[ni*2+c2]   = d + 56;
            co_p[ni*2+c2]   = p;
            co_oidx[ni*2+c2]= transOut ? (w*56+h) : p;
        }
    }
    #pragma unroll
    for (int mi=0;mi<2;mi++) {
        #pragma unroll
        for (int half=0;half<2;half++) {
            int ch = m0 + wm*32 + mi*16 + gidq + half*8;
            if (ch >= M) continue;
            float bi = bias ? bias[ch] : 0.f;
            float sc = 1.f, be = 0.f;
            if (bn_s) { sc = bn_s[ch]*rsqrtf(bn_v[ch]+1e-5f); be = bn_b[ch]-bn_m[ch]*sc; }
            long chbase = (long)ch * HW;
            #pragma unroll
            for (int ni=0;ni<4;ni++) {
                #pragma unroll
                for (int c2=0;c2<2;c2++) {
                    int q = ni*2+c2;
                    float v = acc[mi][ni][half*2+c2] + bi;
                    if (bn_s) v = v*sc + be;
                    if (doGelu) v = gelu_f(v);
                    if (emb) v += emb[co_d[q]*DH + ch];
                    out[(long)co_n[q]*obs + chbase + co_oidx[q]] = v;
                    if (out2 && ch < DH)
                        out2[(long)co_n[q]*((long)DH*HW) + chbase + co_p[q]]
                            = v + emb2[co_d[q]*DH + ch];
                }
            }
        }
    }
}

// =================================================================================
// Strip grouped conv as HMMA tf32 GEMM — double-buffered, register-staged gather,
// v3: all per-chunk index divisions replaced by incremental recurrences
//     (k += 16 -> (i,kk) += (5,1) w/ carry; (pos2,rem) 80-wrap; ptr delta).
// Loads/values/MMA order identical to v2 -> bit-identical output.
// =================================================================================
__global__ __launch_bounds__(256, 3) void strip_mma(
    const float* __restrict__ xin, long in_bs,
    const float* __restrict__ Wt, const float* __restrict__ Bias,
    float* __restrict__ out, long out_bs, int transOut)
{
    __shared__ uint32_t As[2][64][17];
    __shared__ uint32_t Bs[2][16][132];

    const int tid  = threadIdx.x;
    const int wid  = tid >> 5;
    const int lane = tid & 31;
    const int gidq = lane >> 2;
    const int tig  = lane & 3;
    const int wm   = wid >> 2;
    const int wn   = wid & 3;

    const int jb   = blockIdx.x * 128;
    const int ci2  = blockIdx.y;

    float acc[2][4][4];
    #pragma unroll
    for (int mi=0;mi<2;mi++)
        #pragma unroll
        for (int ni=0;ni<4;ni++)
            #pragma unroll
            for (int r=0;r<4;r++) acc[mi][ni][r]=0.f;

    const int arow = tid >> 2;
    const int akq  = (tid & 3) * 4;
    const float* wbase = Wt + (long)ci2 * 9408 + (long)arow * 168;

    // fixed per-thread B-column coords (2 k-row slots)
    int bx0_[2];
    int sk[2], skk[2], srem[2];
    const float* ssrc[2];
    {
        int j   = jb + (tid & 31) * 4;
        int n   = j / 112;
        int rem = j - n*112;
        int c1  = rem / 56;
        int x0  = rem % 56;
        long nbase = (long)n*in_bs;
        #pragma unroll
        for (int r = 0; r < 2; r++) {
            bx0_[r] = x0;
            int k = (tid >> 5) + r*8;       // initial k-row (chunk 0)
            sk[r] = k;
            int i  = k/3;
            skk[r] = k - 3*i;
            int f  = ci2*56 + i;
            int p2 = f/80;
            srem[r] = f - p2*80;
            ssrc[r] = xin + nbase + (long)(c1*80 + srem[r])*HW + p2*56;
        }
    }

    float areg[4];
    float breg[2][4];

    auto gatherA = [&](int kc){
        int k0 = kc*16;
        #pragma unroll
        for (int e = 0; e < 4; e++) {
            int k = k0 + akq + e;
            areg[e] = (arow < 56 && k < 168) ? wbase[k] : 0.f;
        }
    };
    auto gatherB = [&](){
        #pragma unroll
        for (int r = 0; r < 2; r++) {
            #pragma unroll
            for (int e = 0; e < 4; e++) breg[r][e] = 0.f;
            if (sk[r] < 168) {
                int xs0 = bx0_[r] + skk[r] - 1;
                #pragma unroll
                for (int e = 0; e < 4; e++) {
                    int xs = xs0 + e;
                    if (xs >= 0 && xs < 56) breg[r][e] = ssrc[r][xs];
                }
            }
        }
    };
    auto advance = [&](){
        #pragma unroll
        for (int r = 0; r < 2; r++) {
            sk[r] += 16;
            int di = 5;
            skk[r] += 1;
            if (skk[r] >= 3) { skk[r] -= 3; di = 6; }
            srem[r] += di;
            long dsrc = (long)di * HW;
            if (srem[r] >= 80) { srem[r] -= 80; dsrc += 56 - (long)80*HW; }
            ssrc[r] += dsrc;
        }
    };
    auto stage = [&](int s){
        #pragma unroll
        for (int e = 0; e < 4; e++) As[s][arow][akq+e] = tf32_rna(areg[e]);
        #pragma unroll
        for (int r = 0; r < 2; r++) {
            uint4 tv;
            tv.x = tf32_rna(breg[r][0]); tv.y = tf32_rna(breg[r][1]);
            tv.z = tf32_rna(breg[r][2]); tv.w = tf32_rna(breg[r][3]);
            *(uint4*)&Bs[s][(tid>>5) + r*8][(tid & 31)*4] = tv;
        }
    };

    gatherA(0); gatherB();
    for (int c = 0; c < 11; c++) {
        const int s = c & 1;
        stage(s);
        if (c < 10) { advance(); gatherA(c+1); gatherB(); }  // LDGs in flight during MMA
        __syncthreads();
        #pragma unroll
        for (int ks = 0; ks < 2; ks++) {
            int kb = ks * 8;
            uint32_t a[2][4];
            #pragma unroll
            for (int mi=0;mi<2;mi++) {
                int mr = wm*32 + mi*16;
                a[mi][0] = As[s][mr+gidq  ][kb+tig  ];
                a[mi][1] = As[s][mr+gidq+8][kb+tig  ];
                a[mi][2] = As[s][mr+gidq  ][kb+tig+4];
                a[mi][3] = As[s][mr+gidq+8][kb+tig+4];
            }
            uint32_t b[4][2];
            #pragma unroll
            for (int ni=0;ni<4;ni++) {
                int nc = wn*32 + ni*8 + gidq;
                b[ni][0] = Bs[s][kb+tig  ][nc];
                b[ni][1] = Bs[s][kb+tig+4][nc];
            }
            #pragma unroll
            for (int mi=0;mi<2;mi++)
                #pragma unroll
                for (int ni=0;ni<4;ni++)
                    mma_tf32(acc[mi][ni], a[mi], b[ni]);
        }
    }

    long co_base[8]; int co_x[8];
    #pragma unroll
    for (int ni=0;ni<4;ni++) {
        #pragma unroll
        for (int c2=0;c2<2;c2++) {
            int j = jb + wn*32 + ni*8 + 2*tig + c2;
            int n   = j / 112;
            int rem = j - n*112;
            int c1  = rem / 56;
            co_x[ni*2+c2]    = rem % 56;
            co_base[ni*2+c2] = (long)n*out_bs + (long)(c1*80 + ci2)*HW;
        }
    }
    #pragma unroll
    for (int mi=0;mi<2;mi++) {
        #pragma unroll
        for (int half=0;half<2;half++) {
            int o2 = wm*32 + mi*16 + gidq + half*8;
            if (o2 >= 56) continue;
            float bv = Bias[ci2*56 + o2];
            #pragma unroll
            for (int ni=0;ni<4;ni++) {
                #pragma unroll
                for (int c2=0;c2<2;c2++) {
                    int q = ni*2+c2;
                    int x = co_x[q];
                    float v = acc[mi][ni][half*2+c2] + bv;
                    out[co_base[q] + (transOut ? (x*56+o2) : (o2*56+x))] = v;
                }
            }
        }
    }
}

// ---------------- depthwise 3x7 + 7x3 + pooled sum (unchanged) ----------------
__global__ void dw_kernel(
    const float* __restrict__ xp,
    const float* __restrict__ w37, const float* __restrict__ w73,
    float* __restrict__ xw_o, float* __restrict__ xh_o,
    float* __restrict__ pool)
{
    __shared__ float sp[62*62];
    __shared__ float s37[21], s73[21];
    __shared__ float red[256];
    int b = blockIdx.x;
    int n = b / 160, c = b % 160;
    int tid = threadIdx.x;
    const float* src = xp + (long)n*CTOT*HW + (long)(DH+c)*HW;
    for (int idx = tid; idx < 62*62; idx += 256) {
        int hp = idx/62, wp = idx%62;
        int h = hp-3, w = wp-3;
        sp[idx] = (h>=0 && h<56 && w>=0 && w<56) ? src[h*56+w] : 0.f;
    }
    if (tid < 21) s37[tid] = w37[c*21+tid];
    else if (tid < 42) s73[tid-21] = w73[c*21+tid-21];
    __syncthreads();

    float local = 0.f;
    long obase = (long)n*DH*HW + (long)c*HW;
    for (int g = tid; g < 784; g += 256) {
        int h  = g / 14;
        int w0 = (g % 14)*4;
        float a1[4] = {0,0,0,0};
        float a2[4] = {0,0,0,0};
        #pragma unroll
        for (int kh=0;kh<3;kh++) {
            float xv[10];
            #pragma unroll
            for (int t=0;t<10;t++) xv[t] = sp[(h+kh+2)*62 + w0 + t];
            #pragma unroll
            for (int kw=0;kw<7;kw++) {
                float wv = s37[kh*7+kw];
                #pragma unroll
                for (int l=0;l<4;l++) a1[l] += xv[kw+l]*wv;
            }
        }
        #pragma unroll
        for (int kh=0;kh<7;kh++) {
            float xv[6];
            #pragma unroll
            for (int t=0;t<6;t++) xv[t] = sp[(h+kh)*62 + w0 + 2 + t];
            #pragma unroll
            for (int kw=0;kw<3;kw++) {
                float wv = s73[kh*3+kw];
                #pragma unroll
                for (int l=0;l<4;l++) a2[l] += xv[kw+l]*wv;
            }
        }
        #pragma unroll
        for (int l=0;l<4;l++) {
            int p = h*56 + w0 + l;
            float cv = sp[(h+3)*62 + (w0+3+l)];
            xw_o[obase + p] = a1[l];
            xh_o[obase + p] = a2[l];
            local += a1[l] + a2[l] + cv;
        }
    }
    red[tid] = local;
    __syncthreads();
    for (int s=128; s>0; s>>=1) { if (tid < s) red[tid] += red[tid+s]; __syncthreads(); }
    if (tid==0) pool[n*DH+c] = red[0];
}

// ---------------- attention MLP + softmax (unchanged) ----------------
__global__ void att_kernel(
    const float* __restrict__ pool,
    const float* __restrict__ fc1w, const float* __restrict__ fc1b,
    const float* __restrict__ fc2w, const float* __restrict__ fc2b,
    float* __restrict__ att)
{
    __shared__ float mean_s[160];
    __shared__ float t1[40];
    int n = blockIdx.x;
    int tid = threadIdx.x;
    if (tid < 160) mean_s[tid] = pool[n*160+tid] * (1.0f/3136.0f);
    __syncthreads();
    if (tid < 40) {
        float s = fc1b[tid];
        for (int c=0;c<160;c++) s += fc1w[tid*160+c]*mean_s[c];
        t1[tid] = gelu_f(s);
    }
    __syncthreads();
    if (tid < 160) {
        float a[3];
        #pragma unroll
        for (int s3=0;s3<3;s3++) {
            int k = tid*3+s3;
            float v = fc2b[k];
            for (int j=0;j<40;j++) v += fc2w[k*40+j]*t1[j];
            a[s3]=v;
        }
        float mx = fmaxf(a[0],fmaxf(a[1],a[2]));
        float e0=expf(a[0]-mx), e1=expf(a[1]-mx), e2=expf(a[2]-mx);
        float inv = 1.f/(e0+e1+e2);
        att[(n*160+tid)*3+0]=e0*inv;
        att[(n*160+tid)*3+1]=e1*inv;
        att[(n*160+tid)*3+2]=e2*inv;
    }
}

// ---------------- x2_out combine (float4 vectorized) ----------------
__global__ void x2out_kernel(
    const float* __restrict__ xp, const float* __restrict__ xw,
    const float* __restrict__ xh, const float* __restrict__ att,
    float* __restrict__ x2o)
{
    long idx4 = (long)blockIdx.x*blockDim.x + threadIdx.x;
    const long total4 = (long)NB*DH*HW/4;
    if (idx4 >= total4) return;
    long idx = idx4 * 4;
    long t = idx / HW;
    int p = (int)(idx - t*HW);
    int c = (int)(t % DH);
    int n = (int)(t / DH);
    const float* a = att + ((long)n*DH + c)*3;
    float a0 = a[0], a1 = a[1], a2 = a[2];
    float4 xh4 = *(const float4*)(xh + idx);
    float4 xw4 = *(const float4*)(xw + idx);
    float4 x24 = *(const float4*)(xp + (long)n*CTOT*HW + (long)(DH+c)*HW + p);
    float4 o;
    o.x = xh4.x*a0 + xw4.x*a1 + x24.x*a2;
    o.y = xh4.y*a0 + xw4.y*a1 + x24.y*a2;
    o.z = xh4.z*a0 + xw4.z*a1 + x24.z*a2;
    o.w = xh4.w*a0 + xw4.w*a1 + x24.w*a2;
    *(float4*)(x2o + idx) = o;
}

// ---------------- launch ----------------
extern "C" void kernel_launch(void* const* d_in, const int* in_sizes, int n_in,
                              void* d_out, int out_size)
{
    const float* x           = (const float*)d_in[0];
    const float* mlp_pre_w   = (const float*)d_in[1];
    const float* mlp_pre_b   = (const float*)d_in[2];
    const float* bn0_s = (const float*)d_in[3];
    const float* bn0_b = (const float*)d_in[4];
    const float* bn0_m = (const float*)d_in[5];
    const float* bn0_v = (const float*)d_in[6];
    const float* proj_h_w = (const float*)d_in[7];
    const float* proj_h_b = (const float*)d_in[8];
    const float* proj_w_w = (const float*)d_in[9];
    const float* proj_w_b = (const float*)d_in[10];
    const float* fuse_h_w = (const float*)d_in[11];
    const float* fuse_w_w = (const float*)d_in[12];
    const float* bnh_s = (const float*)d_in[13];
    const float* bnh_b = (const float*)d_in[14];
    const float* bnh_m = (const float*)d_in[15];
    const float* bnh_v = (const float*)d_in[16];
    const float* fc_h_w = (const float*)d_in[17];
    const float* fc_w_w = (const float*)d_in[18];
    const float* rw1w = (const float*)d_in[19];
    const float* rw1b = (const float*)d_in[20];
    const float* rw2w = (const float*)d_in[21];
    const float* rw2b = (const float*)d_in[22];
    const float* fuse_post_w = (const float*)d_in[23];
    const float* emb_h = (const float*)d_in[24];
    const float* emb_w = (const float*)d_in[25];

    float *xp,*phin,*ph,*ahT,*pw,*x1o,*xw,*xh,*x2o,*pool,*att;
    cudaGetSymbolAddress((void**)&xp,  g_xp);
    cudaGetSymbolAddress((void**)&phin,g_phin);
    cudaGetSymbolAddress((void**)&ph,  g_ph);
    cudaGetSymbolAddress((void**)&ahT, g_ahT);
    cudaGetSymbolAddress((void**)&pw,  g_pw);
    cudaGetSymbolAddress((void**)&x1o, g_x1o);
    cudaGetSymbolAddress((void**)&xw,  g_xw);
    cudaGetSymbolAddress((void**)&xh,  g_xh);
    cudaGetSymbolAddress((void**)&x2o, g_x2o);
    cudaGetSymbolAddress((void**)&pool,g_pool);
    cudaGetSymbolAddress((void**)&att, g_att);

    cudaFuncSetAttribute(gemm_mma, cudaFuncAttributeMaxDynamicSharedMemorySize, SMEM_GEMM);

    const long bsX = (long)CTOT*HW;
    const long bsH = (long)DH*HW;

    // 1) xp = gelu(bn(mlp_pre)) ; phin = x1 + pos_h  (dual output)
    gemm_mma<<<dim3(392,5),256,SMEM_GEMM>>>(mlp_pre_w, 320, mlp_pre_b, x, bsX, x, bsX, 320,
                                  bn0_s,bn0_b,bn0_m,bn0_v, nullptr, xp, bsX, 0, 1,
                                  emb_h, phin);
    // 2) strip-H on phin -> ph
    strip_mma<<<dim3(14,80),256>>>(phin, bsH, proj_h_w, proj_h_b, ph, bsH, 0);
    // 3) ahT = T( gelu(bn_h(fuse_h_w @ [ph;x1])) + pos_w )
    gemm_mma<<<dim3(392,3),256,SMEM_GEMM>>>(fuse_h_w, 160, nullptr, ph, bsH, xp, bsX, 160,
                                  bnh_s,bnh_b,bnh_m,bnh_v, emb_w, ahT, bsH, 1, 1,
                                  nullptr, nullptr);
    // 4) strip-W on ahT -> pw
    strip_mma<<<dim3(14,80),256>>>(ahT, bsH, proj_w_w, proj_w_b, pw, bsH, 1);
    // 5) x1_out = fuse_w_w @ [x1;pw]
    gemm_mma<<<dim3(392,3),256,SMEM_GEMM>>>(fuse_w_w, 160, nullptr, xp, bsX, pw, bsH, 160,
                                  nullptr,nullptr,nullptr,nullptr, nullptr, x1o, bsH, 0, 0,
                                  nullptr, nullptr);
    // 6) depthwise paths + pooled sums
    dw_kernel<<<2560,256>>>(xp, fc_h_w, fc_w_w, xw, xh, pool);
    // 7) attention weights
    att_kernel<<<16,160>>>(pool, rw1w, rw1b, rw2w, rw2b, att);
    // 8) x2_out (float4)
    x2out_kernel<<<(int)(((long)NB*DH*HW/4 + 255)/256),256>>>(xp, xw, xh, att, x2o);
    // 9) out = fuse_post_w @ [x1_out;x2_out]
    gemm_mma<<<dim3(392,5),256,SMEM_GEMM>>>(fuse_post_w, 320, nullptr, x1o, bsH, x2o, bsH, 160,
                                  nullptr,nullptr,nullptr,nullptr, nullptr, (float*)d_out, bsX, 0, 0,
                                  nullptr, nullptr);
}

// round 12
// speedup vs baseline: 1.0880x; 1.0342x over previous
#include <cuda_runtime.h>
#include <math.h>
#include <stdint.h>

#define NB 16
#define CTOT 320
#define DH 160
#define HW 3136

// ---------------- scratch (device globals; no allocation) ----------------
__device__ float g_xp  [NB*CTOT*HW];
__device__ float g_phin[NB*DH*HW];   // x1 + pos_h (precomputed in step-1 epilogue)
__device__ float g_ph  [NB*DH*HW];
__device__ float g_ahT [NB*DH*HW];
__device__ float g_pw  [NB*DH*HW];
__device__ float g_x1o [NB*DH*HW];
__device__ float g_xw  [NB*DH*HW];
__device__ float g_xh  [NB*DH*HW];
__device__ float g_x2o [NB*DH*HW];
__device__ float g_pool[NB*DH];
__device__ float g_att [NB*DH*3];

__device__ __forceinline__ float gelu_f(float v){
    return 0.5f*v*(1.0f+erff(v*0.70710678118654752440f));
}
__device__ __forceinline__ uint32_t tf32_rna(float v){
    uint32_t o;
    asm("cvt.rna.tf32.f32 %0, %1;" : "=r"(o) : "f"(v));
    return o;
}
__device__ __forceinline__ void mma_tf32(float* c, const uint32_t* a, const uint32_t* b){
    asm volatile(
        "mma.sync.aligned.m16n8k8.row.col.f32.tf32.tf32.f32 "
        "{%0,%1,%2,%3}, {%4,%5,%6,%7}, {%8,%9}, {%0,%1,%2,%3};"
        : "+f"(c[0]), "+f"(c[1]), "+f"(c[2]), "+f"(c[3])
        : "r"(a[0]), "r"(a[1]), "r"(a[2]), "r"(a[3]), "r"(b[0]), "r"(b[1]));
}
#define CP16(dst, src) \
    asm volatile("cp.async.ca.shared.global [%0], [%1], 16;" :: "r"(dst), "l"(src))
#define CP_COMMIT() asm volatile("cp.async.commit_group;" ::: "memory")
#define CP_WAIT2()  asm volatile("cp.async.wait_group 2;" ::: "memory")

// R8 (682us) gemm geometry: A stages 4 x [64][20], B stages 4 x [16][136]
#define A_STRIDE 20
#define B_STRIDE 136
#define A_STAGE  (64*A_STRIDE)
#define B_STAGE  (16*B_STRIDE)
#define B_BASE   (4*A_STAGE)
#define SMEM_GEMM ((4*A_STAGE + 4*B_STAGE)*4)

// =================================================================================
// HMMA tf32 GEMM, 4-stage cp.async pipeline, block 64ch x 128cols (R8 config).
// Optional dual output for step 1: out2 = v + emb2 (pos_h fold, ch<160).
// =================================================================================
__global__ __launch_bounds__(256, 2) void gemm_mma(
    const float* __restrict__ Wm, int M,
    const float* __restrict__ bias,
    const float* __restrict__ in0, long bs0,
    const float* __restrict__ in1, long bs1, int split,
    const float* __restrict__ bn_s, const float* __restrict__ bn_b,
    const float* __restrict__ bn_m, const float* __restrict__ bn_v,
    const float* __restrict__ emb,
    float* __restrict__ out, long obs, int transOut, int doGelu,
    const float* __restrict__ emb2, float* __restrict__ out2)
{
    extern __shared__ float smf[];
    uint32_t sbase = (uint32_t)__cvta_generic_to_shared(smf);

    const int tid  = threadIdx.x;
    const int wid  = tid >> 5;
    const int lane = tid & 31;
    const int gidq = lane >> 2;
    const int tig  = lane & 3;
    const int wm   = wid >> 2;
    const int wn   = wid & 3;

    const long gp0 = (long)blockIdx.x * 128;
    const int  m0  = blockIdx.y * 64;

    float acc[2][4][4];
    #pragma unroll
    for (int mi=0;mi<2;mi++)
        #pragma unroll
        for (int ni=0;ni<4;ni++)
            #pragma unroll
            for (int r=0;r<4;r++) acc[mi][ni][r]=0.f;

    const int arow = tid >> 2;
    const int akq  = (tid & 3) * 4;
    int ach = m0 + arow; if (ach > M-1) ach = M-1;
    const float* asrc_base = Wm + (long)ach*320 + akq;

    const long gpb = gp0 + (tid & 31) * 4;
    const int  bn_ = (int)(gpb / HW);
    const int  bp_ = (int)(gpb - (long)bn_ * HW);
    const float* bptr0 = in0 + (long)bn_*bs0 + bp_;
    const float* bptr1 = in1 + (long)bn_*bs1 + bp_;
    const int bkr0 = tid >> 5;

    auto load_chunk = [&](int kc, int s){
        CP16(sbase + (uint32_t)((s*A_STAGE + arow*A_STRIDE + akq)*4),
             asrc_base + kc*16);
        #pragma unroll
        for (int r = 0; r < 2; r++) {
            int kr = bkr0 + r*8;
            int c  = kc*16 + kr;
            const float* src = (c < split) ? (bptr0 + (long)c*HW)
                                           : (bptr1 + (long)(c-split)*HW);
            CP16(sbase + (uint32_t)((B_BASE + s*B_STAGE + kr*B_STRIDE + (tid&31)*4)*4),
                 src);
        }
    };

    #pragma unroll
    for (int i = 0; i < 3; i++) { load_chunk(i, i); CP_COMMIT(); }

    for (int i = 0; i < 20; i++) {
        CP_WAIT2();
        __syncthreads();
        if (i + 3 < 20) load_chunk(i+3, (i+3) & 3);
        CP_COMMIT();

        const int s = i & 3;
        const float* Af = smf + s*A_STAGE;
        const float* Bf = smf + B_BASE + s*B_STAGE;
        #pragma unroll
        for (int ks = 0; ks < 2; ks++) {
            int kb = ks * 8;
            uint32_t a[2][4];
            #pragma unroll
            for (int mi=0;mi<2;mi++) {
                int mr = wm*32 + mi*16;
                a[mi][0] = tf32_rna(Af[(mr+gidq  )*A_STRIDE + kb+tig  ]);
                a[mi][1] = tf32_rna(Af[(mr+gidq+8)*A_STRIDE + kb+tig  ]);
                a[mi][2] = tf32_rna(Af[(mr+gidq  )*A_STRIDE + kb+tig+4]);
                a[mi][3] = tf32_rna(Af[(mr+gidq+8)*A_STRIDE + kb+tig+4]);
            }
            uint32_t b[4][2];
            #pragma unroll
            for (int ni=0;ni<4;ni++) {
                int nc = wn*32 + ni*8 + gidq;
                b[ni][0] = tf32_rna(Bf[(kb+tig  )*B_STRIDE + nc]);
                b[ni][1] = tf32_rna(Bf[(kb+tig+4)*B_STRIDE + nc]);
            }
            #pragma unroll
            for (int mi=0;mi<2;mi++)
                #pragma unroll
                for (int ni=0;ni<4;ni++)
                    mma_tf32(acc[mi][ni], a[mi], b[ni]);
        }
    }

    int co_n[8], co_oidx[8], co_d[8], co_p[8];
    #pragma unroll
    for (int ni=0;ni<4;ni++) {
        #pragma unroll
        for (int c2=0;c2<2;c2++) {
            int j = wn*32 + ni*8 + 2*tig + c2;
            long gp = gp0 + j;
            int n = (int)(gp / HW);
            int p = (int)(gp - (long)n * HW);
            int h = p / 56, w = p % 56;
            int d = w - h; d = min(max(d,-56),56);
            co_n[ni*2+c2]   = n;
            co_d[ni*2+c2]   = d + 56;
            co_p[ni*2+c2]   = p;
            co_oidx[ni*2+c2]= transOut ? (w*56+h) : p;
        }
    }
    #pragma unroll
    for (int mi=0;mi<2;mi++) {
        #pragma unroll
        for (int half=0;half<2;half++) {
            int ch = m0 + wm*32 + mi*16 + gidq + half*8;
            if (ch >= M) continue;
            float bi = bias ? bias[ch] : 0.f;
            float sc = 1.f, be = 0.f;
            if (bn_s) { sc = bn_s[ch]*rsqrtf(bn_v[ch]+1e-5f); be = bn_b[ch]-bn_m[ch]*sc; }
            long chbase = (long)ch * HW;
            #pragma unroll
            for (int ni=0;ni<4;ni++) {
                #pragma unroll
                for (int c2=0;c2<2;c2++) {
                    int q = ni*2+c2;
                    float v = acc[mi][ni][half*2+c2] + bi;
                    if (bn_s) v = v*sc + be;
                    if (doGelu) v = gelu_f(v);
                    if (emb) v += emb[co_d[q]*DH + ch];
                    out[(long)co_n[q]*obs + chbase + co_oidx[q]] = v;
                    if (out2 && ch < DH)
                        out2[(long)co_n[q]*((long)DH*HW) + chbase + co_p[q]]
                            = v + emb2[co_d[q]*DH + ch];
                }
            }
        }
    }
}

// =================================================================================
// Strip grouped conv as HMMA tf32 GEMM (R11 version — passing, 64us/call)
// =================================================================================
__global__ __launch_bounds__(256, 3) void strip_mma(
    const float* __restrict__ xin, long in_bs,
    const float* __restrict__ Wt, const float* __restrict__ Bias,
    float* __restrict__ out, long out_bs, int transOut)
{
    __shared__ uint32_t As[2][64][17];
    __shared__ uint32_t Bs[2][16][132];

    const int tid  = threadIdx.x;
    const int wid  = tid >> 5;
    const int lane = tid & 31;
    const int gidq = lane >> 2;
    const int tig  = lane & 3;
    const int wm   = wid >> 2;
    const int wn   = wid & 3;

    const int jb   = blockIdx.x * 128;
    const int ci2  = blockIdx.y;

    float acc[2][4][4];
    #pragma unroll
    for (int mi=0;mi<2;mi++)
        #pragma unroll
        for (int ni=0;ni<4;ni++)
            #pragma unroll
            for (int r=0;r<4;r++) acc[mi][ni][r]=0.f;

    const int arow = tid >> 2;
    const int akq  = (tid & 3) * 4;
    const float* wbase = Wt + (long)ci2 * 9408 + (long)arow * 168;

    int bx0_[2];
    int sk[2], skk[2], srem[2];
    const float* ssrc[2];
    {
        int j   = jb + (tid & 31) * 4;
        int n   = j / 112;
        int rem = j - n*112;
        int c1  = rem / 56;
        int x0  = rem % 56;
        long nbase = (long)n*in_bs;
        #pragma unroll
        for (int r = 0; r < 2; r++) {
            bx0_[r] = x0;
            int k = (tid >> 5) + r*8;
            sk[r] = k;
            int i  = k/3;
            skk[r] = k - 3*i;
            int f  = ci2*56 + i;
            int p2 = f/80;
            srem[r] = f - p2*80;
            ssrc[r] = xin + nbase + (long)(c1*80 + srem[r])*HW + p2*56;
        }
    }

    float areg[4];
    float breg[2][4];

    auto gatherA = [&](int kc){
        int k0 = kc*16;
        #pragma unroll
        for (int e = 0; e < 4; e++) {
            int k = k0 + akq + e;
            areg[e] = (arow < 56 && k < 168) ? wbase[k] : 0.f;
        }
    };
    auto gatherB = [&](){
        #pragma unroll
        for (int r = 0; r < 2; r++) {
            #pragma unroll
            for (int e = 0; e < 4; e++) breg[r][e] = 0.f;
            if (sk[r] < 168) {
                int xs0 = bx0_[r] + skk[r] - 1;
                #pragma unroll
                for (int e = 0; e < 4; e++) {
                    int xs = xs0 + e;
                    if (xs >= 0 && xs < 56) breg[r][e] = ssrc[r][xs];
                }
            }
        }
    };
    auto advance = [&](){
        #pragma unroll
        for (int r = 0; r < 2; r++) {
            sk[r] += 16;
            int di = 5;
            skk[r] += 1;
            if (skk[r] >= 3) { skk[r] -= 3; di = 6; }
            srem[r] += di;
            long dsrc = (long)di * HW;
            if (srem[r] >= 80) { srem[r] -= 80; dsrc += 56 - (long)80*HW; }
            ssrc[r] += dsrc;
        }
    };
    auto stage = [&](int s){
        #pragma unroll
        for (int e = 0; e < 4; e++) As[s][arow][akq+e] = tf32_rna(areg[e]);
        #pragma unroll
        for (int r = 0; r < 2; r++) {
            uint4 tv;
            tv.x = tf32_rna(breg[r][0]); tv.y = tf32_rna(breg[r][1]);
            tv.z = tf32_rna(breg[r][2]); tv.w = tf32_rna(breg[r][3]);
            *(uint4*)&Bs[s][(tid>>5) + r*8][(tid & 31)*4] = tv;
        }
    };

    gatherA(0); gatherB();
    for (int c = 0; c < 11; c++) {
        const int s = c & 1;
        stage(s);
        if (c < 10) { advance(); gatherA(c+1); gatherB(); }
        __syncthreads();
        #pragma unroll
        for (int ks = 0; ks < 2; ks++) {
            int kb = ks * 8;
            uint32_t a[2][4];
            #pragma unroll
            for (int mi=0;mi<2;mi++) {
                int mr = wm*32 + mi*16;
                a[mi][0] = As[s][mr+gidq  ][kb+tig  ];
                a[mi][1] = As[s][mr+gidq+8][kb+tig  ];
                a[mi][2] = As[s][mr+gidq  ][kb+tig+4];
                a[mi][3] = As[s][mr+gidq+8][kb+tig+4];
            }
            uint32_t b[4][2];
            #pragma unroll
            for (int ni=0;ni<4;ni++) {
                int nc = wn*32 + ni*8 + gidq;
                b[ni][0] = Bs[s][kb+tig  ][nc];
                b[ni][1] = Bs[s][kb+tig+4][nc];
            }
            #pragma unroll
            for (int mi=0;mi<2;mi++)
                #pragma unroll
                for (int ni=0;ni<4;ni++)
                    mma_tf32(acc[mi][ni], a[mi], b[ni]);
        }
    }

    long co_base[8]; int co_x[8];
    #pragma unroll
    for (int ni=0;ni<4;ni++) {
        #pragma unroll
        for (int c2=0;c2<2;c2++) {
            int j = jb + wn*32 + ni*8 + 2*tig + c2;
            int n   = j / 112;
            int rem = j - n*112;
            int c1  = rem / 56;
            co_x[ni*2+c2]    = rem % 56;
            co_base[ni*2+c2] = (long)n*out_bs + (long)(c1*80 + ci2)*HW;
        }
    }
    #pragma unroll
    for (int mi=0;mi<2;mi++) {
        #pragma unroll
        for (int half=0;half<2;half++) {
            int o2 = wm*32 + mi*16 + gidq + half*8;
            if (o2 >= 56) continue;
            float bv = Bias[ci2*56 + o2];
            #pragma unroll
            for (int ni=0;ni<4;ni++) {
                #pragma unroll
                for (int c2=0;c2<2;c2++) {
                    int q = ni*2+c2;
                    int x = co_x[q];
                    float v = acc[mi][ni][half*2+c2] + bv;
                    out[co_base[q] + (transOut ? (x*56+o2) : (o2*56+x))] = v;
                }
            }
        }
    }
}

// ---------------- depthwise 3x7 + 7x3 + pooled sum (unchanged) ----------------
__global__ void dw_kernel(
    const float* __restrict__ xp,
    const float* __restrict__ w37, const float* __restrict__ w73,
    float* __restrict__ xw_o, float* __restrict__ xh_o,
    float* __restrict__ pool)
{
    __shared__ float sp[62*62];
    __shared__ float s37[21], s73[21];
    __shared__ float red[256];
    int b = blockIdx.x;
    int n = b / 160, c = b % 160;
    int tid = threadIdx.x;
    const float* src = xp + (long)n*CTOT*HW + (long)(DH+c)*HW;
    for (int idx = tid; idx < 62*62; idx += 256) {
        int hp = idx/62, wp = idx%62;
        int h = hp-3, w = wp-3;
        sp[idx] = (h>=0 && h<56 && w>=0 && w<56) ? src[h*56+w] : 0.f;
    }
    if (tid < 21) s37[tid] = w37[c*21+tid];
    else if (tid < 42) s73[tid-21] = w73[c*21+tid-21];
    __syncthreads();

    float local = 0.f;
    long obase = (long)n*DH*HW + (long)c*HW;
    for (int g = tid; g < 784; g += 256) {
        int h  = g / 14;
        int w0 = (g % 14)*4;
        float a1[4] = {0,0,0,0};
        float a2[4] = {0,0,0,0};
        #pragma unroll
        for (int kh=0;kh<3;kh++) {
            float xv[10];
            #pragma unroll
            for (int t=0;t<10;t++) xv[t] = sp[(h+kh+2)*62 + w0 + t];
            #pragma unroll
            for (int kw=0;kw<7;kw++) {
                float wv = s37[kh*7+kw];
                #pragma unroll
                for (int l=0;l<4;l++) a1[l] += xv[kw+l]*wv;
            }
        }
        #pragma unroll
        for (int kh=0;kh<7;kh++) {
            float xv[6];
            #pragma unroll
            for (int t=0;t<6;t++) xv[t] = sp[(h+kh)*62 + w0 + 2 + t];
            #pragma unroll
            for (int kw=0;kw<3;kw++) {
                float wv = s73[kh*3+kw];
                #pragma unroll
                for (int l=0;l<4;l++) a2[l] += xv[kw+l]*wv;
            }
        }
        #pragma unroll
        for (int l=0;l<4;l++) {
            int p = h*56 + w0 + l;
            float cv = sp[(h+3)*62 + (w0+3+l)];
            xw_o[obase + p] = a1[l];
            xh_o[obase + p] = a2[l];
            local += a1[l] + a2[l] + cv;
        }
    }
    red[tid] = local;
    __syncthreads();
    for (int s=128; s>0; s>>=1) { if (tid < s) red[tid] += red[tid+s]; __syncthreads(); }
    if (tid==0) pool[n*DH+c] = red[0];
}

// ---------------- attention MLP + softmax (unchanged) ----------------
__global__ void att_kernel(
    const float* __restrict__ pool,
    const float* __restrict__ fc1w, const float* __restrict__ fc1b,
    const float* __restrict__ fc2w, const float* __restrict__ fc2b,
    float* __restrict__ att)
{
    __shared__ float mean_s[160];
    __shared__ float t1[40];
    int n = blockIdx.x;
    int tid = threadIdx.x;
    if (tid < 160) mean_s[tid] = pool[n*160+tid] * (1.0f/3136.0f);
    __syncthreads();
    if (tid < 40) {
        float s = fc1b[tid];
        for (int c=0;c<160;c++) s += fc1w[tid*160+c]*mean_s[c];
        t1[tid] = gelu_f(s);
    }
    __syncthreads();
    if (tid < 160) {
        float a[3];
        #pragma unroll
        for (int s3=0;s3<3;s3++) {
            int k = tid*3+s3;
            float v = fc2b[k];
            for (int j=0;j<40;j++) v += fc2w[k*40+j]*t1[j];
            a[s3]=v;
        }
        float mx = fmaxf(a[0],fmaxf(a[1],a[2]));
        float e0=expf(a[0]-mx), e1=expf(a[1]-mx), e2=expf(a[2]-mx);
        float inv = 1.f/(e0+e1+e2);
        att[(n*160+tid)*3+0]=e0*inv;
        att[(n*160+tid)*3+1]=e1*inv;
        att[(n*160+tid)*3+2]=e2*inv;
    }
}

// ---------------- x2_out combine (float4 vectorized) ----------------
__global__ void x2out_kernel(
    const float* __restrict__ xp, const float* __restrict__ xw,
    const float* __restrict__ xh, const float* __restrict__ att,
    float* __restrict__ x2o)
{
    long idx4 = (long)blockIdx.x*blockDim.x + threadIdx.x;
    const long total4 = (long)NB*DH*HW/4;
    if (idx4 >= total4) return;
    long idx = idx4 * 4;
    long t = idx / HW;
    int p = (int)(idx - t*HW);
    int c = (int)(t % DH);
    int n = (int)(t / DH);
    const float* a = att + ((long)n*DH + c)*3;
    float a0 = a[0], a1 = a[1], a2 = a[2];
    float4 xh4 = *(const float4*)(xh + idx);
    float4 xw4 = *(const float4*)(xw + idx);
    float4 x24 = *(const float4*)(xp + (long)n*CTOT*HW + (long)(DH+c)*HW + p);
    float4 o;
    o.x = xh4.x*a0 + xw4.x*a1 + x24.x*a2;
    o.y = xh4.y*a0 + xw4.y*a1 + x24.y*a2;
    o.z = xh4.z*a0 + xw4.z*a1 + x24.z*a2;
    o.w = xh4.w*a0 + xw4.w*a1 + x24.w*a2;
    *(float4*)(x2o + idx) = o;
}

// ---------------- launch (fork/join: x2 arm overlaps x1 arm) ----------------
extern "C" void kernel_launch(void* const* d_in, const int* in_sizes, int n_in,
                              void* d_out, int out_size)
{
    const float* x           = (const float*)d_in[0];
    const float* mlp_pre_w   = (const float*)d_in[1];
    const float* mlp_pre_b   = (const float*)d_in[2];
    const float* bn0_s = (const float*)d_in[3];
    const float* bn0_b = (const float*)d_in[4];
    const float* bn0_m = (const float*)d_in[5];
    const float* bn0_v = (const float*)d_in[6];
    const float* proj_h_w = (const float*)d_in[7];
    const float* proj_h_b = (const float*)d_in[8];
    const float* proj_w_w = (const float*)d_in[9];
    const float* proj_w_b = (const float*)d_in[10];
    const float* fuse_h_w = (const float*)d_in[11];
    const float* fuse_w_w = (const float*)d_in[12];
    const float* bnh_s = (const float*)d_in[13];
    const float* bnh_b = (const float*)d_in[14];
    const float* bnh_m = (const float*)d_in[15];
    const float* bnh_v = (const float*)d_in[16];
    const float* fc_h_w = (const float*)d_in[17];
    const float* fc_w_w = (const float*)d_in[18];
    const float* rw1w = (const float*)d_in[19];
    const float* rw1b = (const float*)d_in[20];
    const float* rw2w = (const float*)d_in[21];
    const float* rw2b = (const float*)d_in[22];
    const float* fuse_post_w = (const float*)d_in[23];
    const float* emb_h = (const float*)d_in[24];
    const float* emb_w = (const float*)d_in[25];

    float *xp,*phin,*ph,*ahT,*pw,*x1o,*xw,*xh,*x2o,*pool,*att;
    cudaGetSymbolAddress((void**)&xp,  g_xp);
    cudaGetSymbolAddress((void**)&phin,g_phin);
    cudaGetSymbolAddress((void**)&ph,  g_ph);
    cudaGetSymbolAddress((void**)&ahT, g_ahT);
    cudaGetSymbolAddress((void**)&pw,  g_pw);
    cudaGetSymbolAddress((void**)&x1o, g_x1o);
    cudaGetSymbolAddress((void**)&xw,  g_xw);
    cudaGetSymbolAddress((void**)&xh,  g_xh);
    cudaGetSymbolAddress((void**)&x2o, g_x2o);
    cudaGetSymbolAddress((void**)&pool,g_pool);
    cudaGetSymbolAddress((void**)&att, g_att);

    cudaFuncSetAttribute(gemm_mma, cudaFuncAttributeMaxDynamicSharedMemorySize, SMEM_GEMM);

    const long bsX = (long)CTOT*HW;
    const long bsH = (long)DH*HW;

    // fork/join resources (host-side only; no device allocation)
    cudaStream_t s2;
    cudaStreamCreate(&s2);
    cudaEvent_t evFork, evJoin;
    cudaEventCreateWithFlags(&evFork, cudaEventDisableTiming);
    cudaEventCreateWithFlags(&evJoin, cudaEventDisableTiming);

    // 1) xp = gelu(bn(mlp_pre)) ; phin = x1 + pos_h  (dual output)
    gemm_mma<<<dim3(392,5),256,SMEM_GEMM>>>(mlp_pre_w, 320, mlp_pre_b, x, bsX, x, bsX, 320,
                                  bn0_s,bn0_b,bn0_m,bn0_v, nullptr, xp, bsX, 0, 1,
                                  emb_h, phin);

    // ---- fork: x2 arm on s2 (dw -> att -> x2out) ----
    cudaEventRecord(evFork, 0);
    cudaStreamWaitEvent(s2, evFork, 0);
    dw_kernel<<<2560,256,0,s2>>>(xp, fc_h_w, fc_w_w, xw, xh, pool);
    att_kernel<<<16,160,0,s2>>>(pool, rw1w, rw1b, rw2w, rw2b, att);
    x2out_kernel<<<(int)(((long)NB*DH*HW/4 + 255)/256),256,0,s2>>>(xp, xw, xh, att, x2o);
    cudaEventRecord(evJoin, s2);

    // ---- x1 arm on main stream ----
    // 2) strip-H on phin -> ph
    strip_mma<<<dim3(14,80),256>>>(phin, bsH, proj_h_w, proj_h_b, ph, bsH, 0);
    // 3) ahT = T( gelu(bn_h(fuse_h_w @ [ph;x1])) + pos_w )
    gemm_mma<<<dim3(392,3),256,SMEM_GEMM>>>(fuse_h_w, 160, nullptr, ph, bsH, xp, bsX, 160,
                                  bnh_s,bnh_b,bnh_m,bnh_v, emb_w, ahT, bsH, 1, 1,
                                  nullptr, nullptr);
    // 4) strip-W on ahT -> pw
    strip_mma<<<dim3(14,80),256>>>(ahT, bsH, proj_w_w, proj_w_b, pw, bsH, 1);
    // 5) x1_out = fuse_w_w @ [x1;pw]
    gemm_mma<<<dim3(392,3),256,SMEM_GEMM>>>(fuse_w_w, 160, nullptr, xp, bsX, pw, bsH, 160,
                                  nullptr,nullptr,nullptr,nullptr, nullptr, x1o, bsH, 0, 0,
                                  nullptr, nullptr);

    // ---- join, then final fuse ----
    cudaStreamWaitEvent(0, evJoin, 0);
    // 9) out = fuse_post_w @ [x1_out;x2_out]
    gemm_mma<<<dim3(392,5),256,SMEM_GEMM>>>(fuse_post_w, 320, nullptr, x1o, bsH, x2o, bsH, 160,
                                  nullptr,nullptr,nullptr,nullptr, nullptr, (float*)d_out, bsX, 0, 0,
                                  nullptr, nullptr);
}